// round 14
// baseline (speedup 1.0000x reference)
#include <cuda_runtime.h>

// DeepFilter: 2 t-values per block, all 128 threads run the heavy filter body.
// spec:  (B=8, 2, T=4096, F=481) f32
// coefs: (B=8, 10, T=4096, 256) f32  (c[0..4]=real taps, c[5..9]=imag taps)

#define NUM_FREQS 256
#define FRAME_SIZE 5
#define T_DIM 4096
#define F_TOTAL 481
#define B_DIM 8
#define NPASS (F_TOTAL - NUM_FREQS)   // 225

__global__ __launch_bounds__(128, 8)
void deepfilter_kernel(const float* __restrict__ spec,
                       const float* __restrict__ coefs,
                       float* __restrict__ out)
{
    const int tid = threadIdx.x;
    const int sub = tid >> 6;              // 0 or 1: which t this thread filters
    const int fx  = tid & 63;              // 0..63
    const int f0  = fx * 4;
    const int t0  = blockIdx.x * 2;
    const int t   = t0 + sub;
    const int b   = blockIdx.y;

    const long spec_ch = (long)T_DIM * F_TOTAL;
    const long spec_b  = 2 * spec_ch;
    const long coef_c  = (long)T_DIM * NUM_FREQS;
    const long coef_b  = 2 * FRAME_SIZE * coef_c;

    const float* sp = spec + (long)b * spec_b;
    float*       op = out  + (long)b * spec_b;

    const float* sp_base = sp + (long)t * F_TOTAL;
    float*       ot_base = op + (long)t * F_TOTAL;

    {
        const float* cf = coefs + (long)b * coef_b + (long)t * NUM_FREQS + f0;

        float ar0 = 0.f, ar1 = 0.f, ar2 = 0.f, ar3 = 0.f;
        float ai0 = 0.f, ai1 = 0.f, ai2 = 0.f, ai3 = 0.f;

        if (t >= FRAME_SIZE - 1) {
            // Bulk path: branch-free, fully unrolled — one big load batch.
            #pragma unroll
            for (int k = 0; k < FRAME_SIZE; k++) {
                const float4 cr = __ldcs((const float4*)(cf + (long)k * coef_c));
                const float4 ci = __ldcs((const float4*)(cf + (long)(FRAME_SIZE + k) * coef_c));

                const float* sr = sp_base + (long)(k - (FRAME_SIZE - 1)) * F_TOTAL + f0;
                const float* si = sr + spec_ch;

                const float sr0 = __ldg(sr + 0), sr1 = __ldg(sr + 1);
                const float sr2 = __ldg(sr + 2), sr3 = __ldg(sr + 3);
                const float si0 = __ldg(si + 0), si1 = __ldg(si + 1);
                const float si2 = __ldg(si + 2), si3 = __ldg(si + 3);

                ar0 = fmaf(sr0, cr.x, fmaf(-si0, ci.x, ar0));
                ar1 = fmaf(sr1, cr.y, fmaf(-si1, ci.y, ar1));
                ar2 = fmaf(sr2, cr.z, fmaf(-si2, ci.z, ar2));
                ar3 = fmaf(sr3, cr.w, fmaf(-si3, ci.w, ar3));

                ai0 = fmaf(si0, cr.x, fmaf(sr0, ci.x, ai0));
                ai1 = fmaf(si1, cr.y, fmaf(sr1, ci.y, ai1));
                ai2 = fmaf(si2, cr.z, fmaf(sr2, ci.z, ai2));
                ai3 = fmaf(si3, cr.w, fmaf(sr3, ci.w, ai3));
            }
        } else {
            // Boundary path: t = 0..3, zero-padded history.
            #pragma unroll
            for (int k = 0; k < FRAME_SIZE; k++) {
                const int ts = t + k - (FRAME_SIZE - 1);
                if (ts >= 0) {
                    const float4 cr = *(const float4*)(cf + (long)k * coef_c);
                    const float4 ci = *(const float4*)(cf + (long)(FRAME_SIZE + k) * coef_c);

                    const float* sr = sp_base + (long)(ts - t) * F_TOTAL + f0;
                    const float* si = sr + spec_ch;

                    const float sr0 = sr[0], sr1 = sr[1], sr2 = sr[2], sr3 = sr[3];
                    const float si0 = si[0], si1 = si[1], si2 = si[2], si3 = si[3];

                    ar0 = fmaf(sr0, cr.x, fmaf(-si0, ci.x, ar0));
                    ar1 = fmaf(sr1, cr.y, fmaf(-si1, ci.y, ar1));
                    ar2 = fmaf(sr2, cr.z, fmaf(-si2, ci.z, ar2));
                    ar3 = fmaf(sr3, cr.w, fmaf(-si3, ci.w, ar3));

                    ai0 = fmaf(si0, cr.x, fmaf(sr0, ci.x, ai0));
                    ai1 = fmaf(si1, cr.y, fmaf(sr1, ci.y, ai1));
                    ai2 = fmaf(si2, cr.z, fmaf(sr2, ci.z, ai2));
                    ai3 = fmaf(si3, cr.w, fmaf(sr3, ci.w, ai3));
                }
            }
        }

        float* outr = ot_base + f0;
        float* outi = outr + spec_ch;
        __stcs(outr + 0, ar0); __stcs(outr + 1, ar1);
        __stcs(outr + 2, ar2); __stcs(outr + 3, ar3);
        __stcs(outi + 0, ai0); __stcs(outi + 1, ai1);
        __stcs(outi + 2, ai2); __stcs(outi + 3, ai3);
    }

    // Passthrough: bins 256..480, both channels, both t-values (900 elems / 128 thr).
    const int total = 2 * 2 * NPASS;   // 900
    for (int i = tid; i < total; i += 128) {
        const int f    = i % NPASS;
        const int rest = i / NPASS;
        const int ch   = rest & 1;
        const int tt   = rest >> 1;
        const long off = (long)ch * spec_ch + (long)(t0 + tt) * F_TOTAL
                       + NUM_FREQS + f;
        __stcs(op + off, __ldg(sp + off));
    }
}

extern "C" void kernel_launch(void* const* d_in, const int* in_sizes, int n_in,
                              void* d_out, int out_size)
{
    const float* spec  = (const float*)d_in[0];
    const float* coefs = (const float*)d_in[1];
    float* out = (float*)d_out;

    dim3 grid(T_DIM / 2, B_DIM);
    deepfilter_kernel<<<grid, 128>>>(spec, coefs, out);
}